// round 1
// baseline (speedup 1.0000x reference)
#include <cuda_runtime.h>
#include <math.h>

// Problem constants (fixed shapes per reference)
#define T_SEQ 16384
#define DDIM  1024

// ---------------- scratch (static device allocations are the sanctioned path) ---
__device__ float    g_xwx[T_SEQ * DDIM];   // X@Wx + bh, 64 MB
__device__ unsigned g_bar;                 // grid barrier counter (memset to 0 per launch)

// ---------------- fp32 SGEMM: C[M,N] = A[M,K] @ B[K,N] + bias[N] ----------------
// BM=BN=128, BK=8, 256 threads, 8x8 per thread. M,N,K multiples of 128/8 assumed.
__global__ __launch_bounds__(256, 2)
void sgemm_bias_kernel(const float* __restrict__ A, const float* __restrict__ B,
                       const float* __restrict__ bias, float* __restrict__ C,
                       int M, int N, int K) {
    __shared__ float As[8][128];
    __shared__ float Bs[8][128];

    const int bx = blockIdx.x;   // N tile
    const int by = blockIdx.y;   // M tile
    const int tid = threadIdx.x;

    // A tile load mapping: 128 rows x 8 cols -> 256 float4 (2 per row)
    const int rowA = tid >> 1;
    const int colA = (tid & 1) * 4;
    // B tile load mapping: 8 rows x 128 cols -> 256 float4 (32 per row)
    const int rowB = tid >> 5;
    const int colB = (tid & 31) * 4;

    const int tr = tid / 16;     // 0..15
    const int tc = tid % 16;     // 0..15

    float accum[8][8];
#pragma unroll
    for (int i = 0; i < 8; i++)
#pragma unroll
        for (int j = 0; j < 8; j++) accum[i][j] = 0.0f;

    const float* Aptr = A + (size_t)(by * 128) * K;
    const float* Bptr = B + bx * 128;

    for (int k0 = 0; k0 < K; k0 += 8) {
        float4 a4 = *(const float4*)(Aptr + (size_t)rowA * K + k0 + colA);
        As[colA + 0][rowA] = a4.x;
        As[colA + 1][rowA] = a4.y;
        As[colA + 2][rowA] = a4.z;
        As[colA + 3][rowA] = a4.w;
        float4 b4 = *(const float4*)(Bptr + (size_t)(k0 + rowB) * N + colB);
        *(float4*)&Bs[rowB][colB] = b4;
        __syncthreads();

#pragma unroll
        for (int k = 0; k < 8; k++) {
            float ra[8], rb[8];
            *(float4*)&ra[0] = *(const float4*)&As[k][tr * 8];
            *(float4*)&ra[4] = *(const float4*)&As[k][tr * 8 + 4];
            *(float4*)&rb[0] = *(const float4*)&Bs[k][tc * 8];
            *(float4*)&rb[4] = *(const float4*)&Bs[k][tc * 8 + 4];
#pragma unroll
            for (int i = 0; i < 8; i++)
#pragma unroll
                for (int j = 0; j < 8; j++)
                    accum[i][j] += ra[i] * rb[j];
        }
        __syncthreads();
    }

    const int cRow = by * 128 + tr * 8;
    const int cCol = bx * 128 + tc * 8;
    float bv[8];
#pragma unroll
    for (int j = 0; j < 8; j++) bv[j] = bias[cCol + j];

#pragma unroll
    for (int i = 0; i < 8; i++) {
        float4 v0, v1;
        v0.x = accum[i][0] + bv[0];
        v0.y = accum[i][1] + bv[1];
        v0.z = accum[i][2] + bv[2];
        v0.w = accum[i][3] + bv[3];
        v1.x = accum[i][4] + bv[4];
        v1.y = accum[i][5] + bv[5];
        v1.z = accum[i][6] + bv[6];
        v1.w = accum[i][7] + bv[7];
        *(float4*)&C[(size_t)(cRow + i) * N + cCol]     = v0;
        *(float4*)&C[(size_t)(cRow + i) * N + cCol + 4] = v1;
    }
}

// ---------------- persistent recurrence kernel --------------------------------
// 64 blocks x 256 threads. Block b owns h-columns [b*16, b*16+16).
// Warp w (0..7) owns columns c0=b*16+2w, c1=c0+1. Wh slice held in registers:
// lane l holds Wh[i][c] for i = k*128 + l*4 + {0..3}, k=0..7 (32 weights/col).
// h_t written directly into d_out's hidden section; grid barrier per step.
#define GBLK 64
#define CPB  16

__global__ __launch_bounds__(256, 1)
void rnn_recurrence_kernel(const float* __restrict__ Wh, float* __restrict__ hidden) {
    __shared__ float h_sh[DDIM];

    const int tid  = threadIdx.x;
    const int lane = tid & 31;
    const int warp = tid >> 5;               // 0..7
    const int c0   = blockIdx.x * CPB + warp * 2;
    const int c1   = c0 + 1;

    // Load the two weight columns into registers (one-time, scattered loads).
    float4 w0[8], w1[8];
#pragma unroll
    for (int k = 0; k < 8; k++) {
        int i = k * 128 + lane * 4;
        w0[k].x = Wh[(size_t)(i + 0) * DDIM + c0];
        w0[k].y = Wh[(size_t)(i + 1) * DDIM + c0];
        w0[k].z = Wh[(size_t)(i + 2) * DDIM + c0];
        w0[k].w = Wh[(size_t)(i + 3) * DDIM + c0];
        w1[k].x = Wh[(size_t)(i + 0) * DDIM + c1];
        w1[k].y = Wh[(size_t)(i + 1) * DDIM + c1];
        w1[k].z = Wh[(size_t)(i + 2) * DDIM + c1];
        w1[k].w = Wh[(size_t)(i + 3) * DDIM + c1];
    }

    for (int t = 0; t < T_SEQ; t++) {
        float acc0 = 0.0f, acc1 = 0.0f;

        if (t > 0) {
            // h_{t-1} was written by other SMs: must bypass (incoherent) L1.
            const float4* hp = (const float4*)(hidden + (size_t)(t - 1) * DDIM);
            float4 hv = __ldcg(hp + tid);          // 256 threads x float4 = 1024
            *(float4*)&h_sh[tid * 4] = hv;
            __syncthreads();

#pragma unroll
            for (int k = 0; k < 8; k++) {
                float4 h4 = *(const float4*)&h_sh[k * 128 + lane * 4];
                acc0 += h4.x * w0[k].x + h4.y * w0[k].y + h4.z * w0[k].z + h4.w * w0[k].w;
                acc1 += h4.x * w1[k].x + h4.y * w1[k].y + h4.z * w1[k].z + h4.w * w1[k].w;
            }
        }

        // Warp reduce both partial dots.
#pragma unroll
        for (int s = 16; s > 0; s >>= 1) {
            acc0 += __shfl_xor_sync(0xffffffffu, acc0, s);
            acc1 += __shfl_xor_sync(0xffffffffu, acc1, s);
        }

        if (lane == 0) {
            hidden[(size_t)t * DDIM + c0] = tanhf(acc0 + g_xwx[(size_t)t * DDIM + c0]);
            hidden[(size_t)t * DDIM + c1] = tanhf(acc1 + g_xwx[(size_t)t * DDIM + c1]);
        }

        if (t < T_SEQ - 1) {
            __syncthreads();                       // all warps' stores done (CTA scope)
            if (tid == 0) {
                __threadfence();                   // release: stores visible GPU-wide
                atomicAdd(&g_bar, 1u);
                const unsigned target = (unsigned)(t + 1) * GBLK;
                while (*((volatile unsigned*)&g_bar) < target) { }
                __threadfence();                   // acquire side
            }
            __syncthreads();                       // publish barrier pass to whole CTA
        }
    }
}

// ---------------- launch ---------------------------------------------------------
extern "C" void kernel_launch(void* const* d_in, const int* in_sizes, int n_in,
                              void* d_out, int out_size) {
    const float* X  = (const float*)d_in[0];  // [T, D]
    const float* Wx = (const float*)d_in[1];  // [D, D]
    const float* Wh = (const float*)d_in[2];  // [D, D]
    const float* Wy = (const float*)d_in[3];  // [D, D]
    const float* bh = (const float*)d_in[4];  // [D]
    const float* by = (const float*)d_in[5];  // [D]

    float* out    = (float*)d_out;
    float* hidden = out;                         // [T, D]
    float* ys     = out + (size_t)T_SEQ * DDIM;  // [T, D]

    float* xwx_ptr = nullptr;
    unsigned* bar_ptr = nullptr;
    cudaGetSymbolAddress((void**)&xwx_ptr, g_xwx);
    cudaGetSymbolAddress((void**)&bar_ptr, g_bar);

    // Reset barrier counter (graph-capturable memset node) so replays are deterministic.
    cudaMemsetAsync(bar_ptr, 0, sizeof(unsigned));

    // 1) XWx = X @ Wx + bh
    {
        dim3 grid(DDIM / 128, T_SEQ / 128);
        sgemm_bias_kernel<<<grid, 256>>>(X, Wx, bh, xwx_ptr, T_SEQ, DDIM, DDIM);
    }

    // 2) Sequential recurrence -> hidden
    rnn_recurrence_kernel<<<GBLK, 256>>>(Wh, hidden);

    // 3) Y = H @ Wy + by
    {
        dim3 grid(DDIM / 128, T_SEQ / 128);
        sgemm_bias_kernel<<<grid, 256>>>(hidden, Wy, by, ys, T_SEQ, DDIM, DDIM);
    }
}

// round 3
// speedup vs baseline: 1.1806x; 1.1806x over previous
#include <cuda_runtime.h>
#include <math.h>

// Problem constants (fixed shapes per reference)
#define T_SEQ 16384
#define DDIM  1024

// ---------------- scratch (static device allocations) ----------------------------
__device__ float    g_xwx[T_SEQ * DDIM];   // X@Wx + bh, 64 MB
__device__ unsigned g_cnt[T_SEQ];          // per-step arrival counters (memset/launch)

// ---------------- fp32 SGEMM: C[M,N] = A[M,K] @ B[K,N] + bias[N] ----------------
__global__ __launch_bounds__(256, 2)
void sgemm_bias_kernel(const float* __restrict__ A, const float* __restrict__ B,
                       const float* __restrict__ bias, float* __restrict__ C,
                       int M, int N, int K) {
    __shared__ float As[8][128];
    __shared__ float Bs[8][128];

    const int bx = blockIdx.x;
    const int by = blockIdx.y;
    const int tid = threadIdx.x;

    const int rowA = tid >> 1;
    const int colA = (tid & 1) * 4;
    const int rowB = tid >> 5;
    const int colB = (tid & 31) * 4;

    const int tr = tid / 16;
    const int tc = tid % 16;

    float accum[8][8];
#pragma unroll
    for (int i = 0; i < 8; i++)
#pragma unroll
        for (int j = 0; j < 8; j++) accum[i][j] = 0.0f;

    const float* Aptr = A + (size_t)(by * 128) * K;
    const float* Bptr = B + bx * 128;

    for (int k0 = 0; k0 < K; k0 += 8) {
        float4 a4 = *(const float4*)(Aptr + (size_t)rowA * K + k0 + colA);
        As[colA + 0][rowA] = a4.x;
        As[colA + 1][rowA] = a4.y;
        As[colA + 2][rowA] = a4.z;
        As[colA + 3][rowA] = a4.w;
        float4 b4 = *(const float4*)(Bptr + (size_t)(k0 + rowB) * N + colB);
        *(float4*)&Bs[rowB][colB] = b4;
        __syncthreads();

#pragma unroll
        for (int k = 0; k < 8; k++) {
            float ra[8], rb[8];
            *(float4*)&ra[0] = *(const float4*)&As[k][tr * 8];
            *(float4*)&ra[4] = *(const float4*)&As[k][tr * 8 + 4];
            *(float4*)&rb[0] = *(const float4*)&Bs[k][tc * 8];
            *(float4*)&rb[4] = *(const float4*)&Bs[k][tc * 8 + 4];
#pragma unroll
            for (int i = 0; i < 8; i++)
#pragma unroll
                for (int j = 0; j < 8; j++)
                    accum[i][j] += ra[i] * rb[j];
        }
        __syncthreads();
    }

    const int cRow = by * 128 + tr * 8;
    const int cCol = bx * 128 + tc * 8;
    float bv[8];
#pragma unroll
    for (int j = 0; j < 8; j++) bv[j] = bias[cCol + j];

#pragma unroll
    for (int i = 0; i < 8; i++) {
        float4 v0, v1;
        v0.x = accum[i][0] + bv[0];
        v0.y = accum[i][1] + bv[1];
        v0.z = accum[i][2] + bv[2];
        v0.w = accum[i][3] + bv[3];
        v1.x = accum[i][4] + bv[4];
        v1.y = accum[i][5] + bv[5];
        v1.z = accum[i][6] + bv[6];
        v1.w = accum[i][7] + bv[7];
        *(float4*)&C[(size_t)(cRow + i) * N + cCol]     = v0;
        *(float4*)&C[(size_t)(cRow + i) * N + cCol + 4] = v1;
    }
}

// ---------------- persistent recurrence kernel --------------------------------
// 64 CTAs x 256 threads (8 warps). CTA b owns h-columns [16b, 16b+16).
// Warp w owns columns c0 = 16b + 2w, c1 = c0+1; Wh columns in registers.
// Each warp is autonomous: loads full h_{t-1} row (8x LDG.128/lane), dots,
// butterfly-reduces (two independent chains, pipelined), tanh, stores, then
// two-level release (smem acq_rel arrival -> one gpu-scope red per CTA).
#define GBLK 64
#define WPB  8

__global__ __launch_bounds__(256, 1)
void rnn_recurrence_kernel(const float* __restrict__ Wh, float* __restrict__ hidden) {
    __shared__ unsigned s_arrive;

    const int tid  = threadIdx.x;
    const int lane = tid & 31;
    const int warp = tid >> 5;               // 0..7
    const int c0   = blockIdx.x * (2 * WPB) + warp * 2;
    const int c1   = c0 + 1;

    if (tid == 0) s_arrive = 0u;
    __syncthreads();
    const unsigned s_arrive_addr = (unsigned)__cvta_generic_to_shared(&s_arrive);

    // One-time: two Wh columns into registers. lane l holds rows k*128+4l..+3.
    float4 w0[8], w1[8];
#pragma unroll
    for (int k = 0; k < 8; k++) {
        int i = k * 128 + lane * 4;
        w0[k].x = Wh[(size_t)(i + 0) * DDIM + c0];
        w0[k].y = Wh[(size_t)(i + 1) * DDIM + c0];
        w0[k].z = Wh[(size_t)(i + 2) * DDIM + c0];
        w0[k].w = Wh[(size_t)(i + 3) * DDIM + c0];
        w1[k].x = Wh[(size_t)(i + 0) * DDIM + c1];
        w1[k].y = Wh[(size_t)(i + 1) * DDIM + c1];
        w1[k].z = Wh[(size_t)(i + 2) * DDIM + c1];
        w1[k].w = Wh[(size_t)(i + 3) * DDIM + c1];
    }

    // Prefetch the t=0 bias (x@Wx + bh) for this warp's two columns.
    float bias = (lane < 2) ? __ldcg(&g_xwx[(size_t)0 * DDIM + c0 + lane]) : 0.0f;

    for (int t = 0; t < T_SEQ; t++) {
        // Issue next step's bias load now; it completes during the barrier wait.
        float bias_next = 0.0f;
        if (t + 1 < T_SEQ && lane < 2)
            bias_next = __ldcg(&g_xwx[(size_t)(t + 1) * DDIM + c0 + lane]);

        float acc0 = 0.0f, acc1 = 0.0f;
        if (t > 0) {
            // Wait for all 64 CTAs to have published h_{t-1}.
            const unsigned* cp = &g_cnt[t - 1];
            unsigned v;
            do {
                asm volatile("ld.acquire.gpu.global.u32 %0, [%1];"
                             : "=r"(v) : "l"(cp));
            } while (v < (unsigned)GBLK);

            // Load full h_{t-1}: 8 independent LDG.128 per lane (L2 hits).
            const float4* hp = (const float4*)(hidden + (size_t)(t - 1) * DDIM);
            float4 h4[8];
#pragma unroll
            for (int k = 0; k < 8; k++)
                h4[k] = __ldcg(hp + k * 32 + lane);

#pragma unroll
            for (int k = 0; k < 8; k++) {
                acc0 += h4[k].x * w0[k].x + h4[k].y * w0[k].y
                      + h4[k].z * w0[k].z + h4[k].w * w0[k].w;
                acc1 += h4[k].x * w1[k].x + h4[k].y * w1[k].y
                      + h4[k].z * w1[k].z + h4[k].w * w1[k].w;
            }
            // Two independent butterfly chains; they interleave in the pipe.
#pragma unroll
            for (int s = 16; s > 0; s >>= 1) {
                acc0 += __shfl_xor_sync(0xffffffffu, acc0, s);
                acc1 += __shfl_xor_sync(0xffffffffu, acc1, s);
            }
        }

        // lanes 0/1 compute tanh of their own column in parallel.
        float hval = 0.0f;
        if (lane < 2) hval = tanhf((lane == 0 ? acc0 : acc1) + bias);
        float h1v = __shfl_sync(0xffffffffu, hval, 1);

        if (lane == 0) {
            float2 hv; hv.x = hval; hv.y = h1v;
            *(float2*)&hidden[(size_t)t * DDIM + c0] = hv;

            if (t < T_SEQ - 1) {
                // CTA-level arrival (release covers our store), last warp
                // escalates to gpu scope on the per-step counter.
                unsigned old;
                asm volatile("atom.acq_rel.cta.shared.add.u32 %0, [%1], 1;"
                             : "=r"(old) : "r"(s_arrive_addr));
                if (old == (unsigned)((t + 1) * WPB - 1)) {
                    asm volatile("red.release.gpu.global.add.u32 [%0], 1;"
                                 :: "l"(&g_cnt[t]));
                }
            }
        }
        bias = bias_next;
    }
}

// ---------------- launch ---------------------------------------------------------
extern "C" void kernel_launch(void* const* d_in, const int* in_sizes, int n_in,
                              void* d_out, int out_size) {
    const float* X  = (const float*)d_in[0];  // [T, D]
    const float* Wx = (const float*)d_in[1];  // [D, D]
    const float* Wh = (const float*)d_in[2];  // [D, D]
    const float* Wy = (const float*)d_in[3];  // [D, D]
    const float* bh = (const float*)d_in[4];  // [D]
    const float* by = (const float*)d_in[5];  // [D]

    float* out    = (float*)d_out;
    float* hidden = out;                         // [T, D]
    float* ys     = out + (size_t)T_SEQ * DDIM;  // [T, D]

    float* xwx_ptr = nullptr;
    unsigned* cnt_ptr = nullptr;
    cudaGetSymbolAddress((void**)&xwx_ptr, g_xwx);
    cudaGetSymbolAddress((void**)&cnt_ptr, g_cnt);

    // Reset per-step counters (graph-capturable memset node).
    cudaMemsetAsync(cnt_ptr, 0, T_SEQ * sizeof(unsigned));

    // 1) XWx = X @ Wx + bh
    {
        dim3 grid(DDIM / 128, T_SEQ / 128);
        sgemm_bias_kernel<<<grid, 256>>>(X, Wx, bh, xwx_ptr, T_SEQ, DDIM, DDIM);
    }

    // 2) Sequential recurrence -> hidden
    rnn_recurrence_kernel<<<GBLK, 256>>>(Wh, hidden);

    // 3) Y = H @ Wy + by
    {
        dim3 grid(DDIM / 128, T_SEQ / 128);
        sgemm_bias_kernel<<<grid, 256>>>(hidden, Wy, by, ys, T_SEQ, DDIM, DDIM);
    }
}